// round 6
// baseline (speedup 1.0000x reference)
#include <cuda_runtime.h>
#include <cuda_bf16.h>
#include <cstdint>

#define BB 64
#define SS 128
#define TT 32
#define HH 1024
#define VV 32000
#define G4 (4*HH)
#define K2 (2*HH)

#define NSTAGE 3
#define BKQ 32
#define SMEM_DYN (NSTAGE*64*36*2*sizeof(float))            // k_gemm_t: 55296 B
#define GATES_SMEM (NSTAGE*(32*36+64*36)*sizeof(float))    // k_gates: 41472 B
#define LOGITS_SMEM (NSTAGE*2*128*40*sizeof(__nv_bfloat16)) // k_gemmL: 61440 B

// ---------------- device scratch ----------------
__device__ __nv_bfloat16 g_boutW[(size_t)VV*HH];
__device__ float g_Wcat2[(size_t)G4*K2];              // interleaved [Wih_ctx | Whh], tf32-rounded
__device__ float g_WihE[(size_t)G4*HH];
__device__ float g_embE[(size_t)TT*BB*G4];
__device__ float g_embA[(size_t)TT*BB*HH];
__device__ float g_W1t[HH*HH];
__device__ float g_rW[HH*HH];
__device__ float g_rA[SS*HH];
__device__ float g_keys[SS*HH];
__device__ float g_qw1[BB*HH];
__device__ float g_qpart[4*BB*HH];
__device__ float g_h[BB*HH];
__device__ float g_c[BB*HH];
__device__ float g_htf[BB*HH];
__device__ float g_x2[2][BB*K2];                      // double-buffered [ctx | h]
__device__ __nv_bfloat16 g_Habf[(size_t)BB*TT*HH];
__device__ float g_gbiasp[G4];

// ---------------- helpers ----------------
__device__ __forceinline__ void mma16816(float* c, const uint32_t* a, const uint32_t* b) {
    asm volatile(
        "mma.sync.aligned.m16n8k16.row.col.f32.bf16.bf16.f32 "
        "{%0,%1,%2,%3}, {%4,%5,%6,%7}, {%8,%9}, {%0,%1,%2,%3};\n"
        : "+f"(c[0]), "+f"(c[1]), "+f"(c[2]), "+f"(c[3])
        : "r"(a[0]), "r"(a[1]), "r"(a[2]), "r"(a[3]), "r"(b[0]), "r"(b[1]));
}
__device__ __forceinline__ void mma1688_tf32(float* c, const uint32_t* a, const uint32_t* b) {
    asm volatile(
        "mma.sync.aligned.m16n8k8.row.col.f32.tf32.tf32.f32 "
        "{%0,%1,%2,%3}, {%4,%5,%6,%7}, {%8,%9}, {%0,%1,%2,%3};\n"
        : "+f"(c[0]), "+f"(c[1]), "+f"(c[2]), "+f"(c[3])
        : "r"(a[0]), "r"(a[1]), "r"(a[2]), "r"(a[3]), "r"(b[0]), "r"(b[1]));
}
__device__ __forceinline__ float to_tf32(float x) {
    uint32_t u;
    asm("cvt.rna.tf32.f32 %0, %1;" : "=r"(u) : "f"(x));
    return __uint_as_float(u);
}
__device__ __forceinline__ float tanh_fast(float x) {
    float y;
    asm("tanh.approx.f32 %0, %1;" : "=f"(y) : "f"(x));
    return y;
}
__device__ __forceinline__ void cp16(float* smem, const float* gmem) {
    uint32_t s = (uint32_t)__cvta_generic_to_shared(smem);
    asm volatile("cp.async.ca.shared.global [%0], [%1], 16;\n" :: "r"(s), "l"(gmem));
}
__device__ __forceinline__ void cp16b(__nv_bfloat16* smem, const __nv_bfloat16* gmem) {
    uint32_t s = (uint32_t)__cvta_generic_to_shared(smem);
    asm volatile("cp.async.ca.shared.global [%0], [%1], 16;\n" :: "r"(s), "l"(gmem));
}
#define CP_COMMIT asm volatile("cp.async.commit_group;\n" ::: "memory")
#define CP_WAIT1  asm volatile("cp.async.wait_group 1;\n" ::: "memory")

// ---------------- prep kernels ----------------
__global__ void k_cvt(const float* __restrict__ src, __nv_bfloat16* __restrict__ dst, size_t n) {
    size_t i = (size_t)blockIdx.x * blockDim.x + threadIdx.x;
    size_t stride = (size_t)gridDim.x * blockDim.x;
    for (; i < n; i += stride) dst[i] = __float2bfloat16(src[i]);
}
__global__ void k_round(const float* __restrict__ src, float* __restrict__ dst, size_t n) {
    size_t i = (size_t)blockIdx.x * blockDim.x + threadIdx.x;
    size_t stride = (size_t)gridDim.x * blockDim.x;
    for (; i < n; i += stride) dst[i] = to_tf32(src[i]);
}
__global__ void k_wcat2(const float* __restrict__ Wih, const float* __restrict__ Whh) {
    size_t total = (size_t)G4 * K2;
    size_t i = (size_t)blockIdx.x * blockDim.x + threadIdx.x;
    size_t stride = (size_t)gridDim.x * blockDim.x;
    for (; i < total; i += stride) {
        int r = (int)(i / K2), c = (int)(i % K2);
        int h = r >> 2, g = r & 3;
        int orig = g * HH + h;
        float v = (c < HH) ? Wih[(size_t)orig * K2 + HH + c]
                           : Whh[(size_t)orig * HH + (c - HH)];
        g_Wcat2[i] = to_tf32(v);
    }
}
__global__ void k_wembE(const float* __restrict__ Wih) {
    size_t total = (size_t)G4 * HH;
    size_t i = (size_t)blockIdx.x * blockDim.x + threadIdx.x;
    size_t stride = (size_t)gridDim.x * blockDim.x;
    for (; i < total; i += stride) {
        int r = (int)(i / HH), c = (int)(i % HH);
        int h = r >> 2, g = r & 3;
        g_WihE[i] = to_tf32(Wih[(size_t)(g * HH + h) * K2 + c]);
    }
}
__global__ void k_gbiasp(const float* __restrict__ bih, const float* __restrict__ bhh) {
    int r = blockIdx.x * blockDim.x + threadIdx.x;
    if (r >= G4) return;
    int h = r >> 2, g = r & 3;
    g_gbiasp[r] = bih[g * HH + h] + bhh[g * HH + h];
}
__global__ void k_embA(const float* __restrict__ emb, const int* __restrict__ target) {
    size_t total = (size_t)TT * BB * HH;
    size_t i = (size_t)blockIdx.x * blockDim.x + threadIdx.x;
    size_t stride = (size_t)gridDim.x * blockDim.x;
    for (; i < total; i += stride) {
        int m = (int)(i / HH), j = (int)(i % HH);
        int t = m >> 6, b = m & 63;
        int tok = target[b * TT + t];
        g_embA[i] = to_tf32(emb[(size_t)tok * HH + j]);
    }
}

// ---------------- pipelined tf32 GEMM pieces ----------------
__device__ __forceinline__ void gemm_load_stage(
    float* As, float* Ws, const float* gA, const float* gW,
    int lda, int ldw, int k0, int tid)
{
    #pragma unroll
    for (int i = 0; i < 4; i++) {
        int c = tid + i * 128;
        int row = c >> 3, col = (c & 7) << 2;
        cp16(As + row * 36 + col, gA + (size_t)row * lda + k0 + col);
        cp16(Ws + row * 36 + col, gW + (size_t)row * ldw + k0 + col);
    }
    CP_COMMIT;
}

__device__ __forceinline__ void gemm_compute_stage(
    const float* As, const float* Ws, float acc[2][4][4],
    int wm, int wn, int gid, int t4)
{
    #pragma unroll
    for (int kk = 0; kk < 32; kk += 8) {
        uint32_t afrag[2][4], bfrag[4][2];
        #pragma unroll
        for (int mi = 0; mi < 2; mi++) {
            int r = wm * 32 + mi * 16 + gid;
            afrag[mi][0] = __float_as_uint(As[r * 36 + kk + t4]);
            afrag[mi][1] = __float_as_uint(As[(r + 8) * 36 + kk + t4]);
            afrag[mi][2] = __float_as_uint(As[r * 36 + kk + t4 + 4]);
            afrag[mi][3] = __float_as_uint(As[(r + 8) * 36 + kk + t4 + 4]);
        }
        #pragma unroll
        for (int ni = 0; ni < 4; ni++) {
            int n = wn * 32 + ni * 8 + gid;
            bfrag[ni][0] = __float_as_uint(Ws[n * 36 + kk + t4]);
            bfrag[ni][1] = __float_as_uint(Ws[n * 36 + kk + t4 + 4]);
        }
        #pragma unroll
        for (int mi = 0; mi < 2; mi++)
            #pragma unroll
            for (int ni = 0; ni < 4; ni++)
                mma1688_tf32(acc[mi][ni], afrag[mi], bfrag[ni]);
    }
}

// generic: C[M,N] = A@W^T (+bias). K per z-chunk; z-chunk offsets A/W by z*K cols,
// C by z*zCstride elements (split-K partials).
__global__ void __launch_bounds__(128) k_gemm_t(
    const float* __restrict__ A, const float* __restrict__ W,
    const float* __restrict__ bias, float* __restrict__ C,
    int M, int N, int K, int lda, int ldw, size_t zCstride)
{
    extern __shared__ float sm[];
    float* AsB = sm;
    float* WsB = sm + NSTAGE * 64 * 36;
    int tid = threadIdx.x;
    int warp = tid >> 5, lane = tid & 31;
    int gid = lane >> 2, t4 = lane & 3;
    int wm = warp & 1, wn = warp >> 1;
    int m0 = blockIdx.y * 64, n0 = blockIdx.x * 64;
    int z = blockIdx.z;
    const float* gA = A + (size_t)m0 * lda + (size_t)z * K;
    const float* gW = W + (size_t)n0 * ldw + (size_t)z * K;
    C += (size_t)z * zCstride;

    float acc[2][4][4] = {};
    int KT = K / BKQ;

    gemm_load_stage(AsB, WsB, gA, gW, lda, ldw, 0, tid);
    gemm_load_stage(AsB + 64*36, WsB + 64*36, gA, gW, lda, ldw, BKQ, tid);

    for (int kt = 0; kt < KT; kt++) {
        CP_WAIT1;
        __syncthreads();
        int s = kt % NSTAGE;
        gemm_compute_stage(AsB + s*64*36, WsB + s*64*36, acc, wm, wn, gid, t4);
        int kn = kt + 2;
        if (kn < KT) {
            int sn = kn % NSTAGE;
            gemm_load_stage(AsB + sn*64*36, WsB + sn*64*36, gA, gW, lda, ldw, kn * BKQ, tid);
        } else {
            CP_COMMIT;
        }
        __syncthreads();
    }

    #pragma unroll
    for (int mi = 0; mi < 2; mi++) {
        int r = m0 + wm * 32 + mi * 16 + gid;
        #pragma unroll
        for (int ni = 0; ni < 4; ni++) {
            int cb = n0 + wn * 32 + ni * 8 + 2 * t4;
            float b0 = bias ? bias[cb] : 0.f;
            float b1 = bias ? bias[cb + 1] : 0.f;
            C[(size_t)r * N + cb]           = acc[mi][ni][0] + b0;
            C[(size_t)r * N + cb + 1]       = acc[mi][ni][1] + b1;
            C[(size_t)(r + 8) * N + cb]     = acc[mi][ni][2] + b0;
            C[(size_t)(r + 8) * N + cb + 1] = acc[mi][ni][3] + b1;
        }
    }
}

// qw1 split-K reduce (+bias)
__global__ void k_qred(const float* __restrict__ b1) {
    int i = blockIdx.x * blockDim.x + threadIdx.x;
    if (i >= BB * HH) return;
    g_qw1[i] = g_qpart[i] + g_qpart[i + BB*HH] + g_qpart[i + 2*BB*HH]
             + g_qpart[i + 3*BB*HH] + b1[i % HH];
}

// ---------------- gates GEMM (BM=32, BN=64, K=2048) + fused LSTM cell ----------------
__global__ void __launch_bounds__(128) k_gates(int t) {
    extern __shared__ float sm[];
    __shared__ float sg[32][68];
    float* AsB = sm;                       // 3 stages of 32x36
    float* WsB = sm + NSTAGE * 32 * 36;    // 3 stages of 64x36
    int tid = threadIdx.x;
    int warp = tid >> 5, lane = tid & 31;
    int gid = lane >> 2, t4 = lane & 3;
    int wn = warp;                         // 0..3, each warp 32x16 of the 32x64 tile
    int n0 = blockIdx.x * 64;
    int m0 = blockIdx.y * 32;
    const float* gA = g_x2[t & 1] + (size_t)m0 * K2;
    const float* gW = g_Wcat2 + (size_t)n0 * K2;

    float acc[2][2][4] = {};
    const int KT = K2 / BKQ;   // 64

    // loader: A 32x32 (256 cp16), W 64x32 (512 cp16) per stage
    auto load_stage = [&](int s, int k0) {
        float* As = AsB + s * 32 * 36;
        float* Ws = WsB + s * 64 * 36;
        #pragma unroll
        for (int i = 0; i < 6; i++) {
            int c = tid + i * 128;
            if (c < 256) {
                int row = c >> 3, col = (c & 7) << 2;
                cp16(As + row * 36 + col, gA + (size_t)row * K2 + k0 + col);
            } else {
                int c2 = c - 256;
                int row = c2 >> 3, col = (c2 & 7) << 2;
                cp16(Ws + row * 36 + col, gW + (size_t)row * K2 + k0 + col);
            }
        }
        CP_COMMIT;
    };

    load_stage(0, 0);
    load_stage(1, BKQ);

    for (int kt = 0; kt < KT; kt++) {
        CP_WAIT1;
        __syncthreads();
        int s = kt % NSTAGE;
        const float* As = AsB + s * 32 * 36;
        const float* Ws = WsB + s * 64 * 36;
        #pragma unroll
        for (int kk = 0; kk < 32; kk += 8) {
            uint32_t afrag[2][4], bfrag[2][2];
            #pragma unroll
            for (int mi = 0; mi < 2; mi++) {
                int r = mi * 16 + gid;
                afrag[mi][0] = __float_as_uint(As[r * 36 + kk + t4]);
                afrag[mi][1] = __float_as_uint(As[(r + 8) * 36 + kk + t4]);
                afrag[mi][2] = __float_as_uint(As[r * 36 + kk + t4 + 4]);
                afrag[mi][3] = __float_as_uint(As[(r + 8) * 36 + kk + t4 + 4]);
            }
            #pragma unroll
            for (int ni = 0; ni < 2; ni++) {
                int n = wn * 16 + ni * 8 + gid;
                bfrag[ni][0] = __float_as_uint(Ws[n * 36 + kk + t4]);
                bfrag[ni][1] = __float_as_uint(Ws[n * 36 + kk + t4 + 4]);
            }
            #pragma unroll
            for (int mi = 0; mi < 2; mi++)
                #pragma unroll
                for (int ni = 0; ni < 2; ni++)
                    mma1688_tf32(acc[mi][ni], afrag[mi], bfrag[ni]);
        }
        int kn = kt + 2;
        if (kn < KT) {
            load_stage(kn % NSTAGE, kn * BKQ);
        } else {
            CP_COMMIT;
        }
        __syncthreads();
    }

    // acc + E -> smem gate tile (rows = 32 batches, cols = 64 interleaved gates)
    const float* E = g_embE + (size_t)t * BB * G4;
    #pragma unroll
    for (int mi = 0; mi < 2; mi++) {
        int r = mi * 16 + gid;
        #pragma unroll
        for (int ni = 0; ni < 2; ni++) {
            int cb = wn * 16 + ni * 8 + 2 * t4;
            int n = n0 + cb;
            sg[r][cb]       = acc[mi][ni][0] + E[(size_t)(m0 + r) * G4 + n];
            sg[r][cb + 1]   = acc[mi][ni][1] + E[(size_t)(m0 + r) * G4 + n + 1];
            sg[r+8][cb]     = acc[mi][ni][2] + E[(size_t)(m0 + r + 8) * G4 + n];
            sg[r+8][cb + 1] = acc[mi][ni][3] + E[(size_t)(m0 + r + 8) * G4 + n + 1];
        }
    }
    __syncthreads();

    // fused LSTM cell: batches [m0, m0+32), h in [n0/4, n0/4+16)
    float* x2next = g_x2[(t + 1) & 1];
    int hloc = tid & 15, b0 = tid >> 4;
    int hbase = n0 >> 2;
    #pragma unroll
    for (int pass = 0; pass < 4; pass++) {
        int brel = b0 + pass * 8;
        int b = m0 + brel;
        float gi = sg[brel][4 * hloc];
        float gf = sg[brel][4 * hloc + 1];
        float gg = sg[brel][4 * hloc + 2];
        float go = sg[brel][4 * hloc + 3];
        int h = hbase + hloc;
        int idx = b * HH + h;
        float si = 1.f / (1.f + __expf(-gi));
        float sf = 1.f / (1.f + __expf(-gf));
        float so = 1.f / (1.f + __expf(-go));
        float cn = sf * g_c[idx] + si * tanhf(gg);
        float hn = so * tanhf(cn);
        g_c[idx] = cn;
        g_h[idx] = hn;
        float ht = to_tf32(hn);
        g_htf[idx] = ht;
        x2next[b * K2 + HH + h] = ht;
        g_Habf[((size_t)b * TT + t) * HH + h] = __float2bfloat16(hn);
    }
}

// ---------------- pipelined bf16 logits GEMM: BM=BN=128, BK=32, 256 thr ----------------
#define LSTR 40   // smem row stride in bf16 (conflict-free)
__global__ void __launch_bounds__(256) k_gemmL(
    const __nv_bfloat16* __restrict__ A,
    const __nv_bfloat16* __restrict__ W,
    const float* __restrict__ bias,
    float* __restrict__ C,
    int M, int N, int K)
{
    extern __shared__ __nv_bfloat16 smb[];
    __nv_bfloat16* AsB = smb;                          // 3 stages of 128xLSTR
    __nv_bfloat16* WsB = smb + NSTAGE * 128 * LSTR;
    int tid = threadIdx.x;
    int warp = tid >> 5, lane = tid & 31;
    int gid = lane >> 2, t4 = lane & 3;
    int wm = warp >> 2, wn = warp & 3;   // 2x4 warps, warp tile 64x32
    int m0 = blockIdx.y * 128, n0 = blockIdx.x * 128;
    const __nv_bfloat16* gA = A + (size_t)m0 * K;
    const __nv_bfloat16* gW = W + (size_t)n0 * K;

    float acc[4][4][4] = {};
    int KT = K / 32;

    auto load_stage = [&](int s, int k0) {
        __nv_bfloat16* As = AsB + s * 128 * LSTR;
        __nv_bfloat16* Ws = WsB + s * 128 * LSTR;
        #pragma unroll
        for (int i = 0; i < 4; i++) {
            int c = tid + i * 256;    // 0..1023
            if (c < 512) {
                int row = c >> 2, col = (c & 3) << 3;
                cp16b(As + row * LSTR + col, gA + (size_t)row * K + k0 + col);
            } else {
                int c2 = c - 512;
                int row = c2 >> 2, col = (c2 & 3) << 3;
                cp16b(Ws + row * LSTR + col, gW + (size_t)row * K + k0 + col);
            }
        }
        CP_COMMIT;
    };

    load_stage(0, 0);
    load_stage(1, 32);

    for (int kt = 0; kt < KT; kt++) {
        CP_WAIT1;
        __syncthreads();
        int s = kt % NSTAGE;
        const __nv_bfloat16* As = AsB + s * 128 * LSTR;
        const __nv_bfloat16* Ws = WsB + s * 128 * LSTR;
        #pragma unroll
        for (int kk = 0; kk < 32; kk += 16) {
            uint32_t afrag[4][4], bfrag[4][2];
            #pragma unroll
            for (int mi = 0; mi < 4; mi++) {
                int r = wm * 64 + mi * 16 + gid;
                afrag[mi][0] = *reinterpret_cast<const uint32_t*>(&As[r * LSTR + kk + 2 * t4]);
                afrag[mi][1] = *reinterpret_cast<const uint32_t*>(&As[(r + 8) * LSTR + kk + 2 * t4]);
                afrag[mi][2] = *reinterpret_cast<const uint32_t*>(&As[r * LSTR + kk + 2 * t4 + 8]);
                afrag[mi][3] = *reinterpret_cast<const uint32_t*>(&As[(r + 8) * LSTR + kk + 2 * t4 + 8]);
            }
            #pragma unroll
            for (int ni = 0; ni < 4; ni++) {
                int n = wn * 32 + ni * 8 + gid;
                bfrag[ni][0] = *reinterpret_cast<const uint32_t*>(&Ws[n * LSTR + kk + 2 * t4]);
                bfrag[ni][1] = *reinterpret_cast<const uint32_t*>(&Ws[n * LSTR + kk + 2 * t4 + 8]);
            }
            #pragma unroll
            for (int mi = 0; mi < 4; mi++)
                #pragma unroll
                for (int ni = 0; ni < 4; ni++)
                    mma16816(acc[mi][ni], afrag[mi], bfrag[ni]);
        }
        int kn = kt + 2;
        if (kn < KT) {
            load_stage(kn % NSTAGE, kn * 32);
        } else {
            CP_COMMIT;
        }
        __syncthreads();
    }

    #pragma unroll
    for (int mi = 0; mi < 4; mi++) {
        int r = m0 + wm * 64 + mi * 16 + gid;
        #pragma unroll
        for (int ni = 0; ni < 4; ni++) {
            int cb = n0 + wn * 32 + ni * 8 + 2 * t4;
            float b0 = bias[cb];
            float b1 = bias[cb + 1];
            C[(size_t)r * N + cb]           = acc[mi][ni][0] + b0;
            C[(size_t)r * N + cb + 1]       = acc[mi][ni][1] + b1;
            C[(size_t)(r + 8) * N + cb]     = acc[mi][ni][2] + b0;
            C[(size_t)(r + 8) * N + cb + 1] = acc[mi][ni][3] + b1;
        }
    }
}

// ---------------- fused attention ----------------
__global__ void __launch_bounds__(256) k_attn(
    const float* __restrict__ enc,
    const float* __restrict__ Vw,
    const float* __restrict__ Vb,
    float* __restrict__ attn_out,
    int t)
{
    __shared__ float q[HH];
    __shared__ float vw[HH];
    __shared__ float sc[SS];
    __shared__ float red[128];
    int b = blockIdx.x;
    int tid = threadIdx.x;

    for (int j = tid; j < HH; j += 256) { q[j] = g_qw1[b * HH + j]; vw[j] = Vw[j]; }
    __syncthreads();

    int warp = tid >> 5, lane = tid & 31;
    for (int s = warp; s < SS; s += 8) {
        const float* kp = &g_keys[s * HH];
        float p = 0.f;
        for (int j = lane; j < HH; j += 32)
            p = fmaf(vw[j], tanh_fast(q[j] + kp[j]), p);
        #pragma unroll
        for (int o = 16; o; o >>= 1) p += __shfl_xor_sync(0xffffffffu, p, o);
        if (lane == 0) sc[s] = p + Vb[0];
    }
    __syncthreads();

    if (tid < 128) red[tid] = sc[tid];
    __syncthreads();
    for (int w = 64; w > 0; w >>= 1) {
        if (tid < w) red[tid] = fmaxf(red[tid], red[tid + w]);
        __syncthreads();
    }
    float mx = red[0];
    __syncthreads();
    if (tid < 128) { float e = __expf(sc[tid] - mx); sc[tid] = e; red[tid] = e; }
    __syncthreads();
    for (int w = 64; w > 0; w >>= 1) {
        if (tid < w) red[tid] += red[tid + w];
        __syncthreads();
    }
    float inv = 1.f / red[0];
    if (tid < 128) {
        float a = sc[tid] * inv;
        sc[tid] = a;
        attn_out[((size_t)t * BB + b) * SS + tid] = a;
    }
    __syncthreads();

    float* x2cur = g_x2[t & 1];
    for (int j = tid; j < HH; j += 256) {
        const float* ep = enc + (size_t)b * SS * HH + j;
        float a0 = 0.f, a1 = 0.f, a2 = 0.f, a3 = 0.f;
        #pragma unroll 4
        for (int s = 0; s < SS; s += 4) {
            a0 = fmaf(sc[s],     ep[(size_t)s * HH],       a0);
            a1 = fmaf(sc[s + 1], ep[(size_t)(s + 1) * HH], a1);
            a2 = fmaf(sc[s + 2], ep[(size_t)(s + 2) * HH], a2);
            a3 = fmaf(sc[s + 3], ep[(size_t)(s + 3) * HH], a3);
        }
        x2cur[b * K2 + j] = to_tf32((a0 + a1) + (a2 + a3));
    }
}

// ---------------- misc ----------------
__global__ void k_seed() {
    int idx = blockIdx.x * blockDim.x + threadIdx.x;
    if (idx >= BB * HH) return;
    int b = idx / HH, h = idx % HH;
    float ht = to_tf32(g_h[idx]);
    g_htf[idx] = ht;
    g_x2[0][b * K2 + HH + h] = ht;
}
__global__ void k_copyhc(float* __restrict__ oh, float* __restrict__ oc) {
    int idx = blockIdx.x * blockDim.x + threadIdx.x;
    if (idx >= BB * HH) return;
    oh[idx] = g_h[idx];
    oc[idx] = g_c[idx];
}

// ---------------- log-softmax ----------------
__global__ void __launch_bounds__(256) k_logsoftmax(float* __restrict__ logits) {
    int r = blockIdx.x;
    float* row = logits + (size_t)r * VV;
    float m = -1e30f, s = 0.f;
    for (int v = threadIdx.x; v < VV; v += 256) {
        float x = row[v];
        float nm = fmaxf(m, x);
        s = s * __expf(m - nm) + __expf(x - nm);
        m = nm;
    }
    __shared__ float sm_[256], ssum[256];
    sm_[threadIdx.x] = m; ssum[threadIdx.x] = s;
    __syncthreads();
    for (int w = 128; w > 0; w >>= 1) {
        if (threadIdx.x < w) {
            float m1 = sm_[threadIdx.x], s1 = ssum[threadIdx.x];
            float m2 = sm_[threadIdx.x + w], s2 = ssum[threadIdx.x + w];
            float nm = fmaxf(m1, m2);
            sm_[threadIdx.x] = nm;
            ssum[threadIdx.x] = s1 * __expf(m1 - nm) + s2 * __expf(m2 - nm);
        }
        __syncthreads();
    }
    float lse = sm_[0] + __logf(ssum[0]);
    for (int v = threadIdx.x; v < VV; v += 256) row[v] -= lse;
}

// ---------------- host ----------------
static void launch_gemm_t(const float* A, const float* W, const float* bias,
                          float* C, int M, int N, int K) {
    dim3 grid(N / 64, M / 64, 1);
    k_gemm_t<<<grid, 128, SMEM_DYN>>>(A, W, bias, C, M, N, K, K, K, 0);
}

extern "C" void kernel_launch(void* const* d_in, const int* in_sizes, int n_in,
                              void* d_out, int out_size) {
    (void)in_sizes; (void)n_in; (void)out_size;
    const float* enc    = (const float*)d_in[0];
    const float* encH   = (const float*)d_in[1];
    const float* encC   = (const float*)d_in[2];
    const int*   target = (const int*)d_in[4];
    const float* emb    = (const float*)d_in[5];
    const float* W1     = (const float*)d_in[6];
    const float* b1     = (const float*)d_in[7];
    const float* W2     = (const float*)d_in[8];
    const float* b2     = (const float*)d_in[9];
    const float* Vw     = (const float*)d_in[10];
    const float* Vb     = (const float*)d_in[11];
    const float* Wih    = (const float*)d_in[12];
    const float* Whh    = (const float*)d_in[13];
    const float* bih    = (const float*)d_in[14];
    const float* bhh    = (const float*)d_in[15];
    const float* outW   = (const float*)d_in[16];
    const float* outb   = (const float*)d_in[17];
    const float* br1W   = (const float*)d_in[18];
    const float* br1b   = (const float*)d_in[19];
    const float* br2W   = (const float*)d_in[20];
    const float* br2b   = (const float*)d_in[21];

    float* out = (float*)d_out;
    float* out_logp = out;
    float* out_h    = out + (size_t)BB * TT * VV;
    float* out_c    = out_h + BB * HH;
    float* out_attn = out_c + BB * HH;

    static bool attr_done = false;
    if (!attr_done) {
        cudaFuncSetAttribute(k_gemm_t, cudaFuncAttributeMaxDynamicSharedMemorySize, (int)SMEM_DYN);
        cudaFuncSetAttribute(k_gates,  cudaFuncAttributeMaxDynamicSharedMemorySize, (int)GATES_SMEM);
        cudaFuncSetAttribute(k_gemmL,  cudaFuncAttributeMaxDynamicSharedMemorySize, (int)LOGITS_SMEM);
        attr_done = true;
    }

    void *pboutW, *pkeys, *ph, *pc, *pHabf, *pW1t, *prW, *prA, *pembA, *pembE, *pWihE, *pgbiasp, *phtf, *pqpart;
    cudaGetSymbolAddress(&pboutW, g_boutW);
    cudaGetSymbolAddress(&pkeys, g_keys);
    cudaGetSymbolAddress(&ph, g_h);
    cudaGetSymbolAddress(&pc, g_c);
    cudaGetSymbolAddress(&pHabf, g_Habf);
    cudaGetSymbolAddress(&pW1t, g_W1t);
    cudaGetSymbolAddress(&prW, g_rW);
    cudaGetSymbolAddress(&prA, g_rA);
    cudaGetSymbolAddress(&pembA, g_embA);
    cudaGetSymbolAddress(&pembE, g_embE);
    cudaGetSymbolAddress(&pWihE, g_WihE);
    cudaGetSymbolAddress(&pgbiasp, g_gbiasp);
    cudaGetSymbolAddress(&phtf, g_htf);
    cudaGetSymbolAddress(&pqpart, g_qpart);

    // ---- prep ----
    k_cvt<<<4096, 256>>>(outW, (__nv_bfloat16*)pboutW, (size_t)VV * HH);
    k_wcat2<<<4096, 256>>>(Wih, Whh);
    k_wembE<<<4096, 256>>>(Wih);
    k_gbiasp<<<(G4 + 255) / 256, 256>>>(bih, bhh);
    k_embA<<<2048, 256>>>(emb, target);
    k_round<<<1024, 256>>>(W1, (float*)pW1t, (size_t)HH * HH);

    // E = embA @ WihE^T + gbias_perm
    launch_gemm_t((float*)pembA, (float*)pWihE, (float*)pgbiasp, (float*)pembE,
                  TT * BB, G4, HH);

    // ---- bridge + keys ----
    k_round<<<256, 256>>>(encH, (float*)prA, (size_t)BB * HH);
    k_round<<<1024, 256>>>(br1W, (float*)prW, (size_t)HH * HH);
    launch_gemm_t((float*)prA, (float*)prW, br1b, (float*)ph, BB, HH, HH);

    k_round<<<256, 256>>>(encC, (float*)prA, (size_t)BB * HH);
    k_round<<<1024, 256>>>(br2W, (float*)prW, (size_t)HH * HH);
    launch_gemm_t((float*)prA, (float*)prW, br2b, (float*)pc, BB, HH, HH);

    k_round<<<512, 256>>>(enc, (float*)prA, (size_t)SS * HH);
    k_round<<<1024, 256>>>(W2, (float*)prW, (size_t)HH * HH);
    launch_gemm_t((float*)prA, (float*)prW, b2, (float*)pkeys, SS, HH, HH);

    k_seed<<<BB * HH / 256, 256>>>();

    // ---- recurrent steps ----
    for (int t = 0; t < TT; t++) {
        // qw1 split-K x4: one launch, grid.z = chunk
        {
            dim3 grid(HH / 64, BB / 64, 4);
            k_gemm_t<<<grid, 128, SMEM_DYN>>>((float*)phtf, (float*)pW1t, nullptr,
                                              (float*)pqpart, BB, HH, HH / 4, HH, HH,
                                              (size_t)BB * HH);
        }
        k_qred<<<BB * HH / 256, 256>>>(b1);
        k_attn<<<BB, 256>>>(enc, Vw, Vb, out_attn, t);
        k_gates<<<dim3(G4 / 64, 2), 128, GATES_SMEM>>>(t);
    }

    k_copyhc<<<BB * HH / 256, 256>>>(out_h, out_c);

    // ---- logits + log-softmax ----
    {
        dim3 grid(VV / 128, BB * TT / 128);
        k_gemmL<<<grid, 256, LOGITS_SMEM>>>((__nv_bfloat16*)pHabf, (__nv_bfloat16*)pboutW,
                                            outb, out_logp, BB * TT, VV, HH);
    }
    k_logsoftmax<<<BB * TT, 256>>>(out_logp);
}

// round 7
// speedup vs baseline: 1.3292x; 1.3292x over previous
#include <cuda_runtime.h>
#include <cuda_bf16.h>
#include <cstdint>

#define BB 64
#define SS 128
#define TT 32
#define HH 1024
#define VV 32000
#define G4 (4*HH)
#define K2 (2*HH)

#define NSTAGE 3
#define BKQ 32
#define SMEM_DYN (NSTAGE*64*36*2*sizeof(float))             // 55296 B (k_gemm_t / k_chain)
#define LOGITS_SMEM (NSTAGE*2*128*40*sizeof(__nv_bfloat16)) // 61440 B (k_gemmL)

// ---------------- device scratch ----------------
__device__ __nv_bfloat16 g_boutW[(size_t)VV*HH];
__device__ float g_Wcat2[(size_t)G4*K2];          // interleaved [Wih_ctx | Whh], tf32-rounded
__device__ float g_WihE[(size_t)G4*HH];
__device__ float g_embE[(size_t)TT*BB*G4];
__device__ float g_embA[(size_t)TT*BB*HH];
__device__ float g_W1t[HH*HH];
__device__ float g_rW[HH*HH];
__device__ float g_rA[SS*HH];
__device__ float g_keys[SS*HH];
__device__ float g_qpart[4*BB*HH];
__device__ float g_h[BB*HH];
__device__ float g_c[BB*HH];
__device__ float g_htf[BB*HH];
__device__ float g_x2[2][BB*K2];
__device__ __nv_bfloat16 g_Habf[(size_t)BB*TT*HH];
__device__ float g_gbiasp[G4];
__device__ unsigned g_bar;

// ---------------- helpers ----------------
__device__ __forceinline__ void mma16816(float* c, const uint32_t* a, const uint32_t* b) {
    asm volatile(
        "mma.sync.aligned.m16n8k16.row.col.f32.bf16.bf16.f32 "
        "{%0,%1,%2,%3}, {%4,%5,%6,%7}, {%8,%9}, {%0,%1,%2,%3};\n"
        : "+f"(c[0]), "+f"(c[1]), "+f"(c[2]), "+f"(c[3])
        : "r"(a[0]), "r"(a[1]), "r"(a[2]), "r"(a[3]), "r"(b[0]), "r"(b[1]));
}
__device__ __forceinline__ void mma1688_tf32(float* c, const uint32_t* a, const uint32_t* b) {
    asm volatile(
        "mma.sync.aligned.m16n8k8.row.col.f32.tf32.tf32.f32 "
        "{%0,%1,%2,%3}, {%4,%5,%6,%7}, {%8,%9}, {%0,%1,%2,%3};\n"
        : "+f"(c[0]), "+f"(c[1]), "+f"(c[2]), "+f"(c[3])
        : "r"(a[0]), "r"(a[1]), "r"(a[2]), "r"(a[3]), "r"(b[0]), "r"(b[1]));
}
__device__ __forceinline__ float to_tf32(float x) {
    uint32_t u;
    asm("cvt.rna.tf32.f32 %0, %1;" : "=r"(u) : "f"(x));
    return __uint_as_float(u);
}
__device__ __forceinline__ float tanh_fast(float x) {
    float y;
    asm("tanh.approx.f32 %0, %1;" : "=f"(y) : "f"(x));
    return y;
}
__device__ __forceinline__ void cp16(float* smem, const float* gmem) {
    uint32_t s = (uint32_t)__cvta_generic_to_shared(smem);
    asm volatile("cp.async.ca.shared.global [%0], [%1], 16;\n" :: "r"(s), "l"(gmem));
}
// L1-bypassing copy for data mutated across blocks within one kernel (L1 is not coherent)
__device__ __forceinline__ void cp16cg(float* smem, const float* gmem) {
    uint32_t s = (uint32_t)__cvta_generic_to_shared(smem);
    asm volatile("cp.async.cg.shared.global [%0], [%1], 16;\n" :: "r"(s), "l"(gmem));
}
__device__ __forceinline__ void cp16b(__nv_bfloat16* smem, const __nv_bfloat16* gmem) {
    uint32_t s = (uint32_t)__cvta_generic_to_shared(smem);
    asm volatile("cp.async.ca.shared.global [%0], [%1], 16;\n" :: "r"(s), "l"(gmem));
}
#define CP_COMMIT asm volatile("cp.async.commit_group;\n" ::: "memory")
#define CP_WAIT1  asm volatile("cp.async.wait_group 1;\n" ::: "memory")

// ---------------- prep kernels ----------------
__global__ void k_cvt(const float* __restrict__ src, __nv_bfloat16* __restrict__ dst, size_t n) {
    size_t i = (size_t)blockIdx.x * blockDim.x + threadIdx.x;
    size_t stride = (size_t)gridDim.x * blockDim.x;
    for (; i < n; i += stride) dst[i] = __float2bfloat16(src[i]);
}
__global__ void k_round(const float* __restrict__ src, float* __restrict__ dst, size_t n) {
    size_t i = (size_t)blockIdx.x * blockDim.x + threadIdx.x;
    size_t stride = (size_t)gridDim.x * blockDim.x;
    for (; i < n; i += stride) dst[i] = to_tf32(src[i]);
}
__global__ void k_wcat2(const float* __restrict__ Wih, const float* __restrict__ Whh) {
    size_t total = (size_t)G4 * K2;
    size_t i = (size_t)blockIdx.x * blockDim.x + threadIdx.x;
    size_t stride = (size_t)gridDim.x * blockDim.x;
    for (; i < total; i += stride) {
        int r = (int)(i / K2), c = (int)(i % K2);
        int h = r >> 2, g = r & 3;
        int orig = g * HH + h;
        float v = (c < HH) ? Wih[(size_t)orig * K2 + HH + c]
                           : Whh[(size_t)orig * HH + (c - HH)];
        g_Wcat2[i] = to_tf32(v);
    }
}
__global__ void k_wembE(const float* __restrict__ Wih) {
    size_t total = (size_t)G4 * HH;
    size_t i = (size_t)blockIdx.x * blockDim.x + threadIdx.x;
    size_t stride = (size_t)gridDim.x * blockDim.x;
    for (; i < total; i += stride) {
        int r = (int)(i / HH), c = (int)(i % HH);
        int h = r >> 2, g = r & 3;
        g_WihE[i] = to_tf32(Wih[(size_t)(g * HH + h) * K2 + c]);
    }
}
__global__ void k_gbiasp(const float* __restrict__ bih, const float* __restrict__ bhh) {
    int r = blockIdx.x * blockDim.x + threadIdx.x;
    if (r >= G4) return;
    int h = r >> 2, g = r & 3;
    g_gbiasp[r] = bih[g * HH + h] + bhh[g * HH + h];
}
__global__ void k_embA(const float* __restrict__ emb, const int* __restrict__ target) {
    size_t total = (size_t)TT * BB * HH;
    size_t i = (size_t)blockIdx.x * blockDim.x + threadIdx.x;
    size_t stride = (size_t)gridDim.x * blockDim.x;
    for (; i < total; i += stride) {
        int m = (int)(i / HH), j = (int)(i % HH);
        int t = m >> 6, b = m & 63;
        int tok = target[b * TT + t];
        g_embA[i] = to_tf32(emb[(size_t)tok * HH + j]);
    }
}
__global__ void k_reset() { g_bar = 0; }

// ---------------- pipelined tf32 GEMM (prep only): C = A@W^T + bias ----------------
__device__ __forceinline__ void gemm_load_stage(
    float* As, float* Ws, const float* gA, const float* gW, int K, int k0, int tid)
{
    #pragma unroll
    for (int i = 0; i < 4; i++) {
        int c = tid + i * 128;
        int row = c >> 3, col = (c & 7) << 2;
        cp16(As + row * 36 + col, gA + (size_t)row * K + k0 + col);
        cp16(Ws + row * 36 + col, gW + (size_t)row * K + k0 + col);
    }
    CP_COMMIT;
}
__device__ __forceinline__ void gemm_compute_stage(
    const float* As, const float* Ws, float acc[2][4][4],
    int wm, int wn, int gid, int t4)
{
    #pragma unroll
    for (int kk = 0; kk < 32; kk += 8) {
        uint32_t afrag[2][4], bfrag[4][2];
        #pragma unroll
        for (int mi = 0; mi < 2; mi++) {
            int r = wm * 32 + mi * 16 + gid;
            afrag[mi][0] = __float_as_uint(As[r * 36 + kk + t4]);
            afrag[mi][1] = __float_as_uint(As[(r + 8) * 36 + kk + t4]);
            afrag[mi][2] = __float_as_uint(As[r * 36 + kk + t4 + 4]);
            afrag[mi][3] = __float_as_uint(As[(r + 8) * 36 + kk + t4 + 4]);
        }
        #pragma unroll
        for (int ni = 0; ni < 4; ni++) {
            int n = wn * 32 + ni * 8 + gid;
            bfrag[ni][0] = __float_as_uint(Ws[n * 36 + kk + t4]);
            bfrag[ni][1] = __float_as_uint(Ws[n * 36 + kk + t4 + 4]);
        }
        #pragma unroll
        for (int mi = 0; mi < 2; mi++)
            #pragma unroll
            for (int ni = 0; ni < 4; ni++)
                mma1688_tf32(acc[mi][ni], afrag[mi], bfrag[ni]);
    }
}
__global__ void __launch_bounds__(128) k_gemm_t(
    const float* __restrict__ A, const float* __restrict__ W,
    const float* __restrict__ bias, float* __restrict__ C,
    int M, int N, int K)
{
    extern __shared__ float sm[];
    float* AsB = sm;
    float* WsB = sm + NSTAGE * 64 * 36;
    int tid = threadIdx.x;
    int warp = tid >> 5, lane = tid & 31;
    int gid = lane >> 2, t4 = lane & 3;
    int wm = warp & 1, wn = warp >> 1;
    int m0 = blockIdx.y * 64, n0 = blockIdx.x * 64;
    const float* gA = A + (size_t)m0 * K;
    const float* gW = W + (size_t)n0 * K;

    float acc[2][4][4] = {};
    int KT = K / BKQ;

    gemm_load_stage(AsB, WsB, gA, gW, K, 0, tid);
    gemm_load_stage(AsB + 64*36, WsB + 64*36, gA, gW, K, BKQ, tid);

    for (int kt = 0; kt < KT; kt++) {
        CP_WAIT1;
        __syncthreads();
        int s = kt % NSTAGE;
        gemm_compute_stage(AsB + s*64*36, WsB + s*64*36, acc, wm, wn, gid, t4);
        int kn = kt + 2;
        if (kn < KT) {
            int sn = kn % NSTAGE;
            gemm_load_stage(AsB + sn*64*36, WsB + sn*64*36, gA, gW, K, kn * BKQ, tid);
        } else {
            CP_COMMIT;
        }
    }

    #pragma unroll
    for (int mi = 0; mi < 2; mi++) {
        int r = m0 + wm * 32 + mi * 16 + gid;
        #pragma unroll
        for (int ni = 0; ni < 4; ni++) {
            int cb = n0 + wn * 32 + ni * 8 + 2 * t4;
            float b0 = bias ? bias[cb] : 0.f;
            float b1 = bias ? bias[cb + 1] : 0.f;
            C[(size_t)r * N + cb]           = acc[mi][ni][0] + b0;
            C[(size_t)r * N + cb + 1]       = acc[mi][ni][1] + b1;
            C[(size_t)(r + 8) * N + cb]     = acc[mi][ni][2] + b0;
            C[(size_t)(r + 8) * N + cb + 1] = acc[mi][ni][3] + b1;
        }
    }
}

// ================= fused persistent recurrent chain =================
// 64 blocks x 256 threads. Per step: phase1 qw1 split-K x4 (64 tiles),
// phase2 attention (block==batch), phase3 gates GEMM + fused LSTM cell.
// Grid barrier between phases; cross-block mutable data via .cg (L2-coherent).
__device__ __forceinline__ void gsync(unsigned& nbar) {
    nbar += 64;
    __syncthreads();
    __threadfence();
    if (threadIdx.x == 0) {
        atomicAdd(&g_bar, 1u);
        while (*(volatile unsigned*)&g_bar < nbar) { }
        __threadfence();
    }
    __syncthreads();
}

__global__ void __launch_bounds__(256) k_chain(
    const float* __restrict__ enc, const float* __restrict__ Vw,
    const float* __restrict__ Vb,  const float* __restrict__ b1,
    float* __restrict__ attn_out)
{
    extern __shared__ float smd[];
    __shared__ float sg[64][68];
    __shared__ float qsh[HH];
    __shared__ float vwsh[HH];
    __shared__ float sc[SS];
    __shared__ float red[128];

    float* AsB = smd;
    float* WsB = smd + NSTAGE * 64 * 36;

    const int tid = threadIdx.x;
    const int warp = tid >> 5, lane = tid & 31;
    const int gid = lane >> 2, t4 = lane & 3;
    const int wm = warp & 1, wn = warp >> 1;        // 2 x 4 warp grid
    const int blk = blockIdx.x;                      // 0..63
    unsigned nbar = 0;

    // Vw is constant across steps
    for (int j = tid; j < HH; j += 256) vwsh[j] = Vw[j];

    for (int t = 0; t < TT; t++) {
        // ---------- phase 1: qw1 partials (BM=64, BN=64, K=256 per z) ----------
        {
            const int z  = blk >> 4;
            const int n0 = (blk & 15) * 64;
            const float* gA = g_htf + z * 256;                        // lda = HH
            const float* gW = g_W1t + (size_t)n0 * HH + z * 256;      // ldw = HH
            float acc[2][2][4] = {};
            const int KT = 8;

            auto load = [&](int s, int k0) {
                float* As = AsB + s * 64 * 36;
                float* Ws = WsB + s * 64 * 36;
                #pragma unroll
                for (int i = 0; i < 4; i++) {
                    int c = tid + i * 256;
                    int idx = c & 511;
                    int row = idx >> 3, col = (idx & 7) << 2;
                    if (c < 512) cp16cg(As + row * 36 + col, gA + (size_t)row * HH + k0 + col);
                    else         cp16cg(Ws + row * 36 + col, gW + (size_t)row * HH + k0 + col);
                }
                CP_COMMIT;
            };
            load(0, 0); load(1, BKQ);

            for (int kt = 0; kt < KT; kt++) {
                CP_WAIT1;
                __syncthreads();
                int s = kt % NSTAGE;
                const float* As = AsB + s * 64 * 36;
                const float* Ws = WsB + s * 64 * 36;
                #pragma unroll
                for (int kk = 0; kk < 32; kk += 8) {
                    uint32_t af[2][4], bf[2][2];
                    #pragma unroll
                    for (int mi = 0; mi < 2; mi++) {
                        int r = wm * 32 + mi * 16 + gid;
                        af[mi][0] = __float_as_uint(As[r * 36 + kk + t4]);
                        af[mi][1] = __float_as_uint(As[(r + 8) * 36 + kk + t4]);
                        af[mi][2] = __float_as_uint(As[r * 36 + kk + t4 + 4]);
                        af[mi][3] = __float_as_uint(As[(r + 8) * 36 + kk + t4 + 4]);
                    }
                    #pragma unroll
                    for (int ni = 0; ni < 2; ni++) {
                        int n = wn * 16 + ni * 8 + gid;
                        bf[ni][0] = __float_as_uint(Ws[n * 36 + kk + t4]);
                        bf[ni][1] = __float_as_uint(Ws[n * 36 + kk + t4 + 4]);
                    }
                    #pragma unroll
                    for (int mi = 0; mi < 2; mi++)
                        #pragma unroll
                        for (int ni = 0; ni < 2; ni++)
                            mma1688_tf32(acc[mi][ni], af[mi], bf[ni]);
                }
                int kn = kt + 2;
                if (kn < KT) load(kn % NSTAGE, kn * BKQ);
                else CP_COMMIT;
            }

            float* qp = g_qpart + (size_t)z * BB * HH;
            #pragma unroll
            for (int mi = 0; mi < 2; mi++) {
                int r = wm * 32 + mi * 16 + gid;
                #pragma unroll
                for (int ni = 0; ni < 2; ni++) {
                    int cb = n0 + wn * 16 + ni * 8 + 2 * t4;
                    qp[(size_t)r * HH + cb]           = acc[mi][ni][0];
                    qp[(size_t)r * HH + cb + 1]       = acc[mi][ni][1];
                    qp[(size_t)(r + 8) * HH + cb]     = acc[mi][ni][2];
                    qp[(size_t)(r + 8) * HH + cb + 1] = acc[mi][ni][3];
                }
            }
        }
        gsync(nbar);

        // ---------- phase 2: attention for batch b = blk ----------
        {
            const int b = blk;
            for (int j = tid; j < HH; j += 256) {
                float q = __ldcg(&g_qpart[b * HH + j])
                        + __ldcg(&g_qpart[BB * HH + b * HH + j])
                        + __ldcg(&g_qpart[2 * BB * HH + b * HH + j])
                        + __ldcg(&g_qpart[3 * BB * HH + b * HH + j])
                        + b1[j];
                qsh[j] = q;
            }
            __syncthreads();

            for (int s = warp; s < SS; s += 8) {
                const float* kp = &g_keys[s * HH];
                float p = 0.f;
                for (int j = lane; j < HH; j += 32)
                    p = fmaf(vwsh[j], tanh_fast(qsh[j] + kp[j]), p);
                #pragma unroll
                for (int o = 16; o; o >>= 1) p += __shfl_xor_sync(0xffffffffu, p, o);
                if (lane == 0) sc[s] = p + Vb[0];
            }
            __syncthreads();

            if (tid < 128) red[tid] = sc[tid];
            __syncthreads();
            for (int w = 64; w > 0; w >>= 1) {
                if (tid < w) red[tid] = fmaxf(red[tid], red[tid + w]);
                __syncthreads();
            }
            float mx = red[0];
            __syncthreads();
            if (tid < 128) { float e = __expf(sc[tid] - mx); sc[tid] = e; red[tid] = e; }
            __syncthreads();
            for (int w = 64; w > 0; w >>= 1) {
                if (tid < w) red[tid] += red[tid + w];
                __syncthreads();
            }
            float inv = 1.f / red[0];
            if (tid < 128) {
                float a = sc[tid] * inv;
                sc[tid] = a;
                attn_out[((size_t)t * BB + b) * SS + tid] = a;
            }
            __syncthreads();

            float* x2cur = g_x2[t & 1];
            for (int j = tid; j < HH; j += 256) {
                const float* ep = enc + (size_t)b * SS * HH + j;
                float a0 = 0.f, a1 = 0.f, a2 = 0.f, a3 = 0.f;
                #pragma unroll 4
                for (int s = 0; s < SS; s += 4) {
                    a0 = fmaf(sc[s],     ep[(size_t)s * HH],       a0);
                    a1 = fmaf(sc[s + 1], ep[(size_t)(s + 1) * HH], a1);
                    a2 = fmaf(sc[s + 2], ep[(size_t)(s + 2) * HH], a2);
                    a3 = fmaf(sc[s + 3], ep[(size_t)(s + 3) * HH], a3);
                }
                x2cur[b * K2 + j] = to_tf32((a0 + a1) + (a2 + a3));
            }
        }
        gsync(nbar);

        // ---------- phase 3: gates GEMM (BM=64, BN=64, K=2048) + LSTM cell ----------
        {
            const int n0 = blk * 64;
            const float* gA = g_x2[t & 1];                         // lda = K2
            const float* gW = g_Wcat2 + (size_t)n0 * K2;           // ldw = K2
            float acc[2][2][4] = {};
            const int KT = K2 / BKQ;   // 64

            auto load = [&](int s, int k0) {
                float* As = AsB + s * 64 * 36;
                float* Ws = WsB + s * 64 * 36;
                #pragma unroll
                for (int i = 0; i < 4; i++) {
                    int c = tid + i * 256;
                    int idx = c & 511;
                    int row = idx >> 3, col = (idx & 7) << 2;
                    if (c < 512) cp16cg(As + row * 36 + col, gA + (size_t)row * K2 + k0 + col);
                    else         cp16cg(Ws + row * 36 + col, gW + (size_t)row * K2 + k0 + col);
                }
                CP_COMMIT;
            };
            load(0, 0); load(1, BKQ);

            for (int kt = 0; kt < KT; kt++) {
                CP_WAIT1;
                __syncthreads();
                int s = kt % NSTAGE;
                const float* As = AsB + s * 64 * 36;
                const float* Ws = WsB + s * 64 * 36;
                #pragma unroll
                for (int kk = 0; kk < 32; kk += 8) {
                    uint32_t af[2][4], bf[2][2];
                    #pragma unroll
                    for (int mi = 0; mi < 2; mi++) {
                        int r = wm * 32 + mi * 16 + gid;
                        af[mi][0] = __float_as_uint(As[r * 36 + kk + t4]);
                        af[mi][1] = __float_as_uint(As[(r + 8) * 36 + kk + t4]);
                        af[mi][2] = __float_as_uint(As[r * 36 + kk + t4 + 4]);
                        af[mi][3] = __float_as_uint(As[(r + 8) * 36 + kk + t4 + 4]);
                    }
                    #pragma unroll
                    for (int ni = 0; ni < 2; ni++) {
                        int n = wn * 16 + ni * 8 + gid;
                        bf[ni][0] = __float_as_uint(Ws[n * 36 + kk + t4]);
                        bf[ni][1] = __float_as_uint(Ws[n * 36 + kk + t4 + 4]);
                    }
                    #pragma unroll
                    for (int mi = 0; mi < 2; mi++)
                        #pragma unroll
                        for (int ni = 0; ni < 2; ni++)
                            mma1688_tf32(acc[mi][ni], af[mi], bf[ni]);
                }
                int kn = kt + 2;
                if (kn < KT) load(kn % NSTAGE, kn * BKQ);
                else CP_COMMIT;
            }

            const float* E = g_embE + (size_t)t * BB * G4;
            #pragma unroll
            for (int mi = 0; mi < 2; mi++) {
                int r = wm * 32 + mi * 16 + gid;
                #pragma unroll
                for (int ni = 0; ni < 2; ni++) {
                    int cb = wn * 16 + ni * 8 + 2 * t4;
                    int n = n0 + cb;
                    sg[r][cb]       = acc[mi][ni][0] + E[(size_t)r * G4 + n];
                    sg[r][cb + 1]   = acc[mi][ni][1] + E[(size_t)r * G4 + n + 1];
                    sg[r+8][cb]     = acc[mi][ni][2] + E[(size_t)(r + 8) * G4 + n];
                    sg[r+8][cb + 1] = acc[mi][ni][3] + E[(size_t)(r + 8) * G4 + n + 1];
                }
            }
            __syncthreads();

            // LSTM cell: all 64 batches, h in [n0/4, n0/4+16)
            float* x2next = g_x2[(t + 1) & 1];
            const int hloc = tid & 15, b0 = tid >> 4;    // b0 0..15
            const int hbase = n0 >> 2;
            #pragma unroll
            for (int pass = 0; pass < 4; pass++) {
                int b = b0 + pass * 16;
                float gi = sg[b][4 * hloc];
                float gf = sg[b][4 * hloc + 1];
                float gg = sg[b][4 * hloc + 2];
                float go = sg[b][4 * hloc + 3];
                int h = hbase + hloc;
                int idx = b * HH + h;
                float si = 1.f / (1.f + __expf(-gi));
                float sf = 1.f / (1.f + __expf(-gf));
                float so = 1.f / (1.f + __expf(-go));
                float cn = sf * g_c[idx] + si * tanhf(gg);
                float hn = so * tanhf(cn);
                g_c[idx] = cn;
                g_h[idx] = hn;
                float ht = to_tf32(hn);
                g_htf[idx] = ht;
                x2next[b * K2 + HH + h] = ht;
                g_Habf[((size_t)b * TT + t) * HH + h] = __float2bfloat16(hn);
            }
        }
        gsync(nbar);
    }
}

// ---------------- pipelined bf16 logits GEMM: BM=BN=128, BK=32, 256 thr ----------------
#define LSTR 40
__global__ void __launch_bounds__(256) k_gemmL(
    const __nv_bfloat16* __restrict__ A,
    const __nv_bfloat16* __restrict__ W,
    const float* __restrict__ bias,
    float* __restrict__ C,
    int M, int N, int K)
{
    extern __shared__ __nv_bfloat16 smb[];
    __nv_bfloat16* AsB = smb;
    __nv_bfloat16* WsB = smb + NSTAGE * 128 * LSTR;
    int tid = threadIdx.x;
    int warp = tid >> 5, lane = tid & 31;
    int gid = lane >> 2, t4 = lane & 3;
    int wm = warp >> 2, wn = warp & 3;
    int m0 = blockIdx.y * 128, n0 = blockIdx.x * 128;
    const __nv_bfloat16* gA = A + (size_t)m0 * K;
    const __nv_bfloat16* gW = W + (size_t)n0 * K;

    float acc[4][4][4] = {};
    int KT = K / 32;

    auto load_stage = [&](int s, int k0) {
        __nv_bfloat16* As = AsB + s * 128 * LSTR;
        __nv_bfloat16* Ws = WsB + s * 128 * LSTR;
        #pragma unroll
        for (int i = 0; i < 4; i++) {
            int c = tid + i * 256;
            if (c < 512) {
                int row = c >> 2, col = (c & 3) << 3;
                cp16b(As + row * LSTR + col, gA + (size_t)row * K + k0 + col);
            } else {
                int c2 = c - 512;
                int row = c2 >> 2, col = (c2 & 3) << 3;
                cp16b(Ws + row * LSTR + col, gW + (size_t)row * K + k0 + col);
            }
        }
        CP_COMMIT;
    };

    load_stage(0, 0);
    load_stage(1, 32);

    for (int kt = 0; kt < KT; kt++) {
        CP_WAIT1;
        __syncthreads();
        int s = kt % NSTAGE;
        const __nv_bfloat16* As = AsB + s * 128 * LSTR;
        const __nv_bfloat16* Ws = WsB + s * 128 * LSTR;
        #pragma unroll
        for (int kk = 0; kk < 32; kk += 16) {
            uint32_t afrag[4][4], bfrag[4][2];
            #pragma unroll
            for (int mi = 0; mi < 4; mi++) {
                int r = wm * 64 + mi * 16 + gid;
                afrag[mi][0] = *reinterpret_cast<const uint32_t*>(&As[r * LSTR + kk + 2 * t4]);
                afrag[mi][1] = *reinterpret_cast<const uint32_t*>(&As[(r + 8) * LSTR + kk + 2 * t4]);
                afrag[mi][2] = *reinterpret_cast<const uint32_t*>(&As[r * LSTR + kk + 2 * t4 + 8]);
                afrag[mi][3] = *reinterpret_cast<const uint32_t*>(&As[(r + 8) * LSTR + kk + 2 * t4 + 8]);
            }
            #pragma unroll
            for (int ni = 0; ni < 4; ni++) {
                int n = wn * 32 + ni * 8 + gid;
                bfrag[ni][0] = *reinterpret_cast<const uint32_t*>(&Ws[n * LSTR + kk + 2 * t4]);
                bfrag[ni][1] = *reinterpret_cast<const uint32_t*>(&Ws[n * LSTR + kk + 2 * t4 + 8]);
            }
            #pragma unroll
            for (int mi = 0; mi < 4; mi++)
                #pragma unroll
                for (int ni = 0; ni < 4; ni++)
                    mma16816(acc[mi][ni], afrag[mi], bfrag[ni]);
        }
        int kn = kt + 2;
        if (kn < KT) load_stage(kn % NSTAGE, kn * 32);
        else CP_COMMIT;
    }

    #pragma unroll
    for (int mi = 0; mi < 4; mi++) {
        int r = m0 + wm * 64 + mi * 16 + gid;
        #pragma unroll
        for (int ni = 0; ni < 4; ni++) {
            int cb = n0 + wn * 32 + ni * 8 + 2 * t4;
            float b0 = bias[cb];
            float b1 = bias[cb + 1];
            C[(size_t)r * N + cb]           = acc[mi][ni][0] + b0;
            C[(size_t)r * N + cb + 1]       = acc[mi][ni][1] + b1;
            C[(size_t)(r + 8) * N + cb]     = acc[mi][ni][2] + b0;
            C[(size_t)(r + 8) * N + cb + 1] = acc[mi][ni][3] + b1;
        }
    }
}

// ---------------- misc ----------------
__global__ void k_seed() {
    int idx = blockIdx.x * blockDim.x + threadIdx.x;
    if (idx >= BB * HH) return;
    int b = idx / HH, h = idx % HH;
    float ht = to_tf32(g_h[idx]);
    g_htf[idx] = ht;
    g_x2[0][b * K2 + HH + h] = ht;
}
__global__ void k_copyhc(float* __restrict__ oh, float* __restrict__ oc) {
    int idx = blockIdx.x * blockDim.x + threadIdx.x;
    if (idx >= BB * HH) return;
    oh[idx] = g_h[idx];
    oc[idx] = g_c[idx];
}

// ---------------- log-softmax ----------------
__global__ void __launch_bounds__(256) k_logsoftmax(float* __restrict__ logits) {
    int r = blockIdx.x;
    float* row = logits + (size_t)r * VV;
    float m = -1e30f, s = 0.f;
    for (int v = threadIdx.x; v < VV; v += 256) {
        float x = row[v];
        float nm = fmaxf(m, x);
        s = s * __expf(m - nm) + __expf(x - nm);
        m = nm;
    }
    __shared__ float sm_[256], ssum[256];
    sm_[threadIdx.x] = m; ssum[threadIdx.x] = s;
    __syncthreads();
    for (int w = 128; w > 0; w >>= 1) {
        if (threadIdx.x < w) {
            float m1 = sm_[threadIdx.x], s1 = ssum[threadIdx.x];
            float m2 = sm_[threadIdx.x + w], s2 = ssum[threadIdx.x + w];
            float nm = fmaxf(m1, m2);
            sm_[threadIdx.x] = nm;
            ssum[threadIdx.x] = s1 * __expf(m1 - nm) + s2 * __expf(m2 - nm);
        }
        __syncthreads();
    }
    float lse = sm_[0] + __logf(ssum[0]);
    for (int v = threadIdx.x; v < VV; v += 256) row[v] -= lse;
}

// ---------------- host ----------------
static void launch_gemm_t(const float* A, const float* W, const float* bias,
                          float* C, int M, int N, int K) {
    dim3 grid(N / 64, M / 64);
    k_gemm_t<<<grid, 128, SMEM_DYN>>>(A, W, bias, C, M, N, K);
}

extern "C" void kernel_launch(void* const* d_in, const int* in_sizes, int n_in,
                              void* d_out, int out_size) {
    (void)in_sizes; (void)n_in; (void)out_size;
    const float* enc    = (const float*)d_in[0];
    const float* encH   = (const float*)d_in[1];
    const float* encC   = (const float*)d_in[2];
    const int*   target = (const int*)d_in[4];
    const float* emb    = (const float*)d_in[5];
    const float* W1     = (const float*)d_in[6];
    const float* b1     = (const float*)d_in[7];
    const float* W2     = (const float*)d_in[8];
    const float* b2     = (const float*)d_in[9];
    const float* Vw     = (const float*)d_in[10];
    const float* Vb     = (const float*)d_in[11];
    const float* Wih    = (const float*)d_in[12];
    const float* Whh    = (const float*)d_in[13];
    const float* bih    = (const float*)d_in[14];
    const float* bhh    = (const float*)d_in[15];
    const float* outW   = (const float*)d_in[16];
    const float* outb   = (const float*)d_in[17];
    const float* br1W   = (const float*)d_in[18];
    const float* br1b   = (const float*)d_in[19];
    const float* br2W   = (const float*)d_in[20];
    const float* br2b   = (const float*)d_in[21];

    float* out = (float*)d_out;
    float* out_logp = out;
    float* out_h    = out + (size_t)BB * TT * VV;
    float* out_c    = out_h + BB * HH;
    float* out_attn = out_c + BB * HH;

    static bool attr_done = false;
    if (!attr_done) {
        cudaFuncSetAttribute(k_gemm_t, cudaFuncAttributeMaxDynamicSharedMemorySize, (int)SMEM_DYN);
        cudaFuncSetAttribute(k_chain,  cudaFuncAttributeMaxDynamicSharedMemorySize, (int)SMEM_DYN);
        cudaFuncSetAttribute(k_gemmL,  cudaFuncAttributeMaxDynamicSharedMemorySize, (int)LOGITS_SMEM);
        attr_done = true;
    }

    void *pboutW, *pkeys, *ph, *pc, *pHabf, *pW1t, *prW, *prA, *pembA, *pembE, *pWihE, *pgbiasp;
    cudaGetSymbolAddress(&pboutW, g_boutW);
    cudaGetSymbolAddress(&pkeys, g_keys);
    cudaGetSymbolAddress(&ph, g_h);
    cudaGetSymbolAddress(&pc, g_c);
    cudaGetSymbolAddress(&pHabf, g_Habf);
    cudaGetSymbolAddress(&pW1t, g_W1t);
    cudaGetSymbolAddress(&prW, g_rW);
    cudaGetSymbolAddress(&prA, g_rA);
    cudaGetSymbolAddress(&pembA, g_embA);
    cudaGetSymbolAddress(&pembE, g_embE);
    cudaGetSymbolAddress(&pWihE, g_WihE);
    cudaGetSymbolAddress(&pgbiasp, g_gbiasp);

    // ---- prep ----
    k_cvt<<<4096, 256>>>(outW, (__nv_bfloat16*)pboutW, (size_t)VV * HH);
    k_wcat2<<<4096, 256>>>(Wih, Whh);
    k_wembE<<<4096, 256>>>(Wih);
    k_gbiasp<<<(G4 + 255) / 256, 256>>>(bih, bhh);
    k_embA<<<2048, 256>>>(emb, target);
    k_round<<<1024, 256>>>(W1, (float*)pW1t, (size_t)HH * HH);

    // E = embA @ WihE^T + gbias_perm
    launch_gemm_t((float*)pembA, (float*)pWihE, (float*)pgbiasp, (float*)pembE,
                  TT * BB, G4, HH);

    // ---- bridge + keys ----
    k_round<<<256, 256>>>(encH, (float*)prA, (size_t)BB * HH);
    k_round<<<1024, 256>>>(br1W, (float*)prW, (size_t)HH * HH);
    launch_gemm_t((float*)prA, (float*)prW, br1b, (float*)ph, BB, HH, HH);

    k_round<<<256, 256>>>(encC, (float*)prA, (size_t)BB * HH);
    k_round<<<1024, 256>>>(br2W, (float*)prW, (size_t)HH * HH);
    launch_gemm_t((float*)prA, (float*)prW, br2b, (float*)pc, BB, HH, HH);

    k_round<<<512, 256>>>(enc, (float*)prA, (size_t)SS * HH);
    k_round<<<1024, 256>>>(W2, (float*)prW, (size_t)HH * HH);
    launch_gemm_t((float*)prA, (float*)prW, b2, (float*)pkeys, SS, HH, HH);

    k_seed<<<BB * HH / 256, 256>>>();

    // ---- fused recurrent chain (single persistent kernel) ----
    k_reset<<<1, 32>>>();
    k_chain<<<64, 256, SMEM_DYN>>>(enc, Vw, Vb, b1, out_attn);

    k_copyhc<<<BB * HH / 256, 256>>>(out_h, out_c);

    // ---- logits + log-softmax ----
    {
        dim3 grid(VV / 128, BB * TT / 128);
        k_gemmL<<<grid, 256, LOGITS_SMEM>>>((__nv_bfloat16*)pHabf, (__nv_bfloat16*)pboutW,
                                            outb, out_logp, BB * TT, VV, HH);
    }
    k_logsoftmax<<<BB * TT, 256>>>(out_logp);
}